// round 17
// baseline (speedup 1.0000x reference)
#include <cuda_runtime.h>
#include <math.h>

#define NUM_CLASSES 10
#define Hh 480
#define Ww 640
#define SKIP 8
#define GY 60
#define GX 80
#define P  4800
#define NCHUNK (P / 32)                  // 150
#define NMAX 8
#define EPSF 1e-6f
#define INLIER 0.9f
#define RINL (1.0f / 0.9f)
#define GUARD 1.3e-5f
#define VTILE 512
#define CBLK  128                        // candidates per vote block
#define CLANES 64                        // candidate lanes (2 candidates each)
#define NSL 8                            // pixel slices
#define VTHREADS 512
#define VOTE_BX ((P + CBLK - 1) / CBLK)  // 38
#define KD (NUM_CLASSES - 1)

// ---------------- device scratch ----------------
// g_mask / g_bkey are unconditionally overwritten every replay -> no reset needed.
static __device__ unsigned g_mask[NMAX][NCHUNK][NUM_CLASSES]; // class-membership ballots
static __device__ unsigned g_bkey[NMAX][NUM_CLASSES][VOTE_BX]; // per-block winner key

// Inlier predicate pieces. Fast scaled quadratic test; exact IEEE fallback in
// a guard band. Identical arithmetic everywhere -> identical inlier sets.
__device__ __forceinline__ void hv_core(float fcx, float fcy, float4 t,
                                        float& s, float& dotv, float& gd)
{
    float dx = fcx - t.x;
    float dy = fcy - t.y;
    s    = fmaf(dx, dx, dy * dy);
    dotv = fmaf(t.z, dx, t.w * dy);
    float dp = fmaxf(dotv, 0.0f) * RINL;
    gd   = fmaf(dp, dp, -s);
}

__device__ __forceinline__ bool hv_exact(float s, float dotv)
{
    float rd = sqrtf(s) + EPSF;              // exact reference formula
    return (dotv / rd) > INLIER;
}

__device__ __forceinline__ bool hv_inlier(float fcx, float fcy, float4 t)
{
    float s, dotv, gd;
    hv_core(fcx, fcy, t, s, dotv, gd);
    bool inl = gd > 0.0f;
    if (fabsf(gd) < GUARD * s)
        inl = hv_exact(s, dotv);
    return inl;
}

// gather one pixel's (x,y,u,v) from vertex_pred — shared by vote and final.
__device__ __forceinline__ float4 hv_gather_xyuv(const float* __restrict__ vp,
                                                 int n, int p, int k)
{
    int iy = p / GX, ix = p - iy * GX;
    const float* v3 = vp + (size_t)n * Hh * Ww * (3 * NUM_CLASSES)
                         + (size_t)(iy * SKIP * Ww + ix * SKIP) * (3 * NUM_CLASSES) + 3 * k;
    float u = v3[0], v = v3[1];
    float nrm = sqrtf(u * u + v * v) + EPSF;
    return make_float4((float)(ix * SKIP), (float)(iy * SKIP), u / nrm, v / nrm);
}

// ================= K1: parallel label ballots + output zeroing =================
__global__ void __launch_bounds__(256)
hv_mask_kernel(const int* __restrict__ label,
               float* __restrict__ out, int N)
{
    const int n    = blockIdx.y;
    const int warp = threadIdx.x >> 5;
    const int lane = threadIdx.x & 31;
    const int chunk = blockIdx.x * 8 + warp;
    const unsigned FULL = 0xffffffffu;

    const int idx = blockIdx.x * 256 + threadIdx.x;
    if (idx < KD * 40) {
        out[(size_t)N * KD * 14 + (size_t)n * KD * 40 + idx] = 0.0f;
        out[(size_t)N * KD * 54 + (size_t)n * KD * 40 + idx] = 0.0f;
    }

    if (chunk >= NCHUNK) return;
    int p = chunk * 32 + lane;
    int iy = p / GX, ix = p - iy * GX;
    int l = label[(size_t)n * Hh * Ww + iy * SKIP * Ww + ix * SKIP];
    #pragma unroll
    for (int k = 0; k < NUM_CLASSES; k++) {
        unsigned m = __ballot_sync(FULL, l == k);
        if (lane == 0) g_mask[n][chunk][k] = m;
    }
}

// shared list-builder: scan class-k masks -> smem plist (stable p-order).
__device__ __forceinline__ int hv_build_list(int n, int k, short* s_plist,
                                             int* s_choff, int* s_cntk,
                                             int warp, int lane, int nwarps)
{
    const unsigned FULL = 0xffffffffu;
    if (warp == 0) {
        int carry = 0;
        #pragma unroll
        for (int r = 0; r < (NCHUNK + 31) / 32; r++) {
            int j = r * 32 + lane;
            int v = (j < NCHUNK) ? __popc(g_mask[n][j][k]) : 0;
            int incl = v;
            #pragma unroll
            for (int d = 1; d < 32; d <<= 1) {
                int t = __shfl_up_sync(FULL, incl, d);
                if (lane >= d) incl += t;
            }
            if (j < NCHUNK) s_choff[j] = carry + (incl - v);
            carry += __shfl_sync(FULL, incl, 31);
        }
        if (lane == 0) *s_cntk = carry;
    }
    __syncthreads();
    for (int chunk = warp; chunk < NCHUNK; chunk += nwarps) {
        unsigned m = g_mask[n][chunk][k];
        if (m & (1u << lane)) {
            int pos = s_choff[chunk] + __popc(m & ((1u << lane) - 1u));
            s_plist[pos] = (short)(chunk * 32 + lane);
        }
    }
    __syncthreads();
    return *s_cntk;
}

// ================= K2: self-sorting vote (2 cand/thread, deferred suspicion) =================
__global__ void __launch_bounds__(VTHREADS)
hv_vote_kernel(const float* __restrict__ vp)
{
    const int n = blockIdx.z;
    const int k = blockIdx.y + 1;
    const int tid   = threadIdx.x;
    const int warp  = tid >> 5;
    const int lane  = tid & 31;
    const int cl    = tid & (CLANES - 1);        // candidate lane 0..63
    const int slice = tid >> 6;                  // 0..7
    const int c0    = blockIdx.x * CBLK + cl;
    const int c1    = c0 + CLANES;

    __shared__ short    s_plist[P];
    __shared__ int      s_choff[NCHUNK];
    __shared__ int      s_cntk;
    __shared__ float4   sxy[VTILE];
    __shared__ int      s_pcnt[NSL][CLANES][2];
    __shared__ unsigned skey[CLANES];

    const int cnt_k = hv_build_list(n, k, s_plist, s_choff, &s_cntk, warp, lane, 16);

    float fcx0 = 0.f, fcy0 = 0.f, fcx1 = 0.f, fcy1 = 0.f;
    const bool v0 = (c0 < P), v1 = (c1 < P);
    if (v0) { int iy = c0 / GX, ix = c0 - iy * GX; fcx0 = (float)(ix * SKIP); fcy0 = (float)(iy * SKIP); }
    if (v1) { int iy = c1 / GX, ix = c1 - iy * GX; fcx1 = (float)(ix * SKIP); fcy1 = (float)(iy * SKIP); }

    int  cnt0 = 0, cnt1 = 0;
    bool sus0 = false, sus1 = false;

    for (int base = 0; base < cnt_k; base += VTILE) {
        int m = cnt_k - base;
        if (m > VTILE) m = VTILE;
        for (int j = tid; j < m; j += VTHREADS) {
            int p = (int)s_plist[base + j];
            sxy[j] = hv_gather_xyuv(vp, n, p, k);
        }
        __syncthreads();

        // fast loop: no branches, suspicion deferred
        for (int j = slice; j < m; j += NSL) {
            float4 t = sxy[j];
            float sA, dA, gA, sB, dB, gB;
            hv_core(fcx0, fcy0, t, sA, dA, gA);
            hv_core(fcx1, fcy1, t, sB, dB, gB);
            cnt0 += (gA > 0.0f);
            cnt1 += (gB > 0.0f);
            sus0 |= (fabsf(gA) < GUARD * sA);
            sus1 |= (fabsf(gB) < GUARD * sB);
        }
        __syncthreads();
    }

    // rare: a candidate saw a guard-band pair -> recompute its slice exactly
    if (sus0 | sus1) {
        if (sus0) {
            int rc = 0;
            for (int j = slice; j < cnt_k; j += NSL) {
                int p = (int)s_plist[j];
                float4 t = hv_gather_xyuv(vp, n, p, k);
                if (hv_inlier(fcx0, fcy0, t)) rc++;
            }
            cnt0 = rc;
        }
        if (sus1) {
            int rc = 0;
            for (int j = slice; j < cnt_k; j += NSL) {
                int p = (int)s_plist[j];
                float4 t = hv_gather_xyuv(vp, n, p, k);
                if (hv_inlier(fcx1, fcy1, t)) rc++;
            }
            cnt1 = rc;
        }
    }

    s_pcnt[slice][cl][0] = cnt0;
    s_pcnt[slice][cl][1] = cnt1;
    __syncthreads();

    if (slice == 0) {
        int t0 = 0, t1 = 0;
        #pragma unroll
        for (int q = 0; q < NSL; q++) { t0 += s_pcnt[q][cl][0]; t1 += s_pcnt[q][cl][1]; }
        unsigned k0 = v0 ? ((((unsigned)t0) << 13) | (unsigned)(8191 - c0)) : 0u;
        unsigned k1 = v1 ? ((((unsigned)t1) << 13) | (unsigned)(8191 - c1)) : 0u;
        skey[cl] = (k0 > k1) ? k0 : k1;
    }
    __syncthreads();

    for (int s = CLANES / 2; s > 0; s >>= 1) {
        if (tid < s) {
            unsigned o = skey[tid + s];
            if (o > skey[tid]) skey[tid] = o;
        }
        __syncthreads();
    }
    if (tid == 0)
        g_bkey[n][k][blockIdx.x] = skey[0];
}

// ================= K3: reduce keys + winner dsum + epilogue =================
__global__ void __launch_bounds__(256)
hv_final_kernel(const float* __restrict__ vp,
                const float* __restrict__ extents,
                const float* __restrict__ meta,
                float* __restrict__ out, int N)
{
    const int k   = blockIdx.x + 1;
    const int n   = blockIdx.y;
    const int tid = threadIdx.x;
    const int warp = tid >> 5;
    const int lane = tid & 31;
    const unsigned FULL = 0xffffffffu;

    __shared__ short s_plist[P];
    __shared__ int   s_choff[NCHUNK];
    __shared__ int   s_cntk;
    __shared__ float rds[256];

    const int cnt_k = hv_build_list(n, k, s_plist, s_choff, &s_cntk, warp, lane, 8);

    unsigned key = 0u;
    if (tid < VOTE_BX) key = g_bkey[n][k][tid];
    #pragma unroll
    for (int d = 16; d > 0; d >>= 1) {
        unsigned ok = __shfl_down_sync(FULL, key, d);
        if (ok > key) key = ok;
    }
    __shared__ unsigned s_wk[2];
    if ((tid & 31) == 0 && tid < 64) s_wk[tid >> 5] = key;
    __syncthreads();
    unsigned bkey = (s_wk[0] > s_wk[1]) ? s_wk[0] : s_wk[1];

    float votes = (float)(bkey >> 13);
    int   best  = 8191 - (int)(bkey & 8191u);
    int biy = best / GX, bix = best - biy * GX;
    float cx = (float)(bix * SKIP);
    float cy = (float)(biy * SKIP);

    float ds = 0.0f;
    for (int j = tid; j < cnt_k; j += 256) {
        int p = (int)s_plist[j];
        float4 t = hv_gather_xyuv(vp, n, p, k);
        if (hv_inlier(cx, cy, t)) {
            int iy = p / GX, ix = p - iy * GX;
            float w = vp[(size_t)n * Hh * Ww * (3 * NUM_CLASSES)
                         + (size_t)(iy * SKIP * Ww + ix * SKIP) * (3 * NUM_CLASSES) + 3 * k + 2];
            ds += expf(fminf(fmaxf(w, -3.0f), 3.0f));
        }
    }
    rds[tid] = ds;
    __syncthreads();
    for (int s = 128; s > 0; s >>= 1) {
        if (tid < s) rds[tid] += rds[tid + s];
        __syncthreads();
    }

    if (tid == 0) {
        float dsum = rds[0];
        float davg = dsum / fmaxf(votes, 1.0f);
        float cntk = (float)cnt_k;

        bool valid = (votes > 20.0f) && (votes > 0.1f * cntk)
                     && (cntk * (float)(SKIP * SKIP) > 500.0f);

        const float* mt = meta + (size_t)n * 9;
        float fx = mt[0], fy = mt[4], ppx = mt[2], ppy = mt[5];

        float e0 = extents[k * 3 + 0];
        float e1 = extents[k * 3 + 1];
        float e2 = extents[k * 3 + 2];
        float diam = sqrtf(e0 * e0 + e1 * e1 + e2 * e2) + EPSF;

        float hx = 0.5f * diam * fx / fmaxf(davg, EPSF);
        float hy = 0.5f * diam * fy / fmaxf(davg, EPSF);
        float score = valid ? votes : 0.0f;

        float* b = out + ((size_t)n * KD + (k - 1)) * 7;
        b[0] = (float)n;
        b[1] = (float)k;
        b[2] = cx - hx;
        b[3] = cy - hy;
        b[4] = cx + hx;
        b[5] = cy + hy;
        b[6] = score;

        float* ps = out + (size_t)N * KD * 7 + ((size_t)n * KD + (k - 1)) * 7;
        ps[0] = 1.0f; ps[1] = 0.0f; ps[2] = 0.0f; ps[3] = 0.0f;
        ps[4] = (cx - ppx) * davg / fx;
        ps[5] = (cy - ppy) * davg / fy;
        ps[6] = davg;

        out[(size_t)N * KD * 94 + (size_t)n * KD + (k - 1)] = (float)n;
    }
}

// ---------------- launch ----------------
extern "C" void kernel_launch(void* const* d_in, const int* in_sizes, int n_in,
                              void* d_out, int out_size)
{
    const int*   label   = (const int*)d_in[0];
    const float* vp      = (const float*)d_in[1];
    const float* extents = (const float*)d_in[2];
    const float* meta    = (const float*)d_in[4];
    float* out = (float*)d_out;

    int N = in_sizes[4] / 9;
    if (N < 1) N = 1;
    if (N > NMAX) N = NMAX;

    dim3 gm((NCHUNK + 7) / 8, N);
    hv_mask_kernel<<<gm, 256>>>(label, out, N);

    dim3 gv(VOTE_BX, KD, N);
    hv_vote_kernel<<<gv, VTHREADS>>>(vp);

    dim3 gf(KD, N);
    hv_final_kernel<<<gf, 256>>>(vp, extents, meta, out, N);
}